// round 3
// baseline (speedup 1.0000x reference)
#include <cuda_runtime.h>
#include <cuda_bf16.h>

// HybridQLSTM_65481071409480 — GB300 (sm_103a)
//
// Algebraic collapse (verified R2: rel_err = 0.0 exactly):
//     log_softmax(broadcast_to(expectation[..., None], (S,B,T)), axis=-1)
// over a constant row of length T=50 is identically -log(50) for every
// element, independent of ALL inputs. The embedding gather, 512-step LSTM
// scan, and sin() expectation are dead code. Output = constant fill of
// fp32-nearest -log(50) over 819200 floats (3.125 MiB).
//
// R2 ncu: kernel 3.94us, DRAM=0% (writes absorbed in L2), issue=41% —
// launch-overhead bound, not memory bound. R3 change: 4x fewer threads/CTAs
// (200 CTAs x 256 thr x 4 float4 = 64 B/thread, coalesced stride-interleaved)
// to shorten the CTA-dispatch ramp and amortize per-thread setup. Store
// throughput is ~10x under the L2 path cap, so fatter threads cost nothing.

#define UNROLL 4

__global__ void fill_neglog50_kernel(float4* __restrict__ out4, int n4,
                                     float* __restrict__ out_tail, int n_tail) {
    const float v = -3.9120230674743652f;  // fp32-nearest -log(50)
    const float4 v4 = make_float4(v, v, v, v);
    const int nthreads = gridDim.x * blockDim.x;
    int idx = blockIdx.x * blockDim.x + threadIdx.x;

    // Fast path: exactly UNROLL stride-interleaved stores per thread,
    // fully coalesced (each warp writes contiguous 512B per iteration).
    if (n4 == nthreads * UNROLL) {
#pragma unroll
        for (int u = 0; u < UNROLL; u++) {
            out4[idx + u * nthreads] = v4;
        }
    } else {
        // Robust fallback for any size.
        for (int i = idx; i < n4; i += nthreads) {
            out4[i] = v4;
        }
    }
    if (idx < n_tail) {
        out_tail[idx] = v;
    }
}

extern "C" void kernel_launch(void* const* d_in, const int* in_sizes, int n_in,
                              void* d_out, int out_size) {
    (void)d_in; (void)in_sizes; (void)n_in;
    if (out_size <= 0) return;

    float* out = (float*)d_out;
    int n4 = out_size >> 2;           // 204800 for out_size = 819200
    int n_tail = out_size & 3;        // 0 here
    float* tail_ptr = out + (size_t)n4 * 4;

    const int threads = 256;
    // 4 float4 per thread: 204800 / (256*4) = 200 CTAs.
    int blocks = (n4 + threads * UNROLL - 1) / (threads * UNROLL);
    if (blocks > 65535) blocks = 65535;   // fallback loop covers overflow
    if (blocks < 1) blocks = 1;

    fill_neglog50_kernel<<<blocks, threads>>>(
        (float4*)out, n4, tail_ptr, n_tail);
}

// round 4
// speedup vs baseline: 1.4444x; 1.4444x over previous
#include <cuda_runtime.h>
#include <cuda_bf16.h>

// HybridQLSTM_65481071409480 — GB300 (sm_103a)
//
// Algebraic collapse (verified R2/R3: rel_err = 0.0 exactly):
//   log_softmax over a broadcast-constant row of length T=50 is identically
//   -log(50) for every output element, independent of ALL inputs. The
//   embedding gather, 512-step LSTM scan, and sin() expectation are dead
//   code. Output = fill of fp32 -log(50) over 819200 floats (3.125 MiB).
//
// R3 post-mortem: total dur_us is pinned at ~6.6us regardless of kernel
// shape (3.94us vs 4.86us ncu kernels both time 6.6us end-to-end) -> the
// problem sits at the single-launch graph-replay overhead floor. R4 reverts
// to the best-measured config (800 CTAs x 256 thr x one float4/thread, R2)
// with the branchy fast/slow path stripped to minimize instruction count.

__global__ void fill_neglog50_kernel(float4* __restrict__ out4, int n4,
                                     float* __restrict__ out_tail, int n_tail) {
    const float v = -3.9120230674743652f;  // fp32-nearest -log(50)
    const int idx = blockIdx.x * blockDim.x + threadIdx.x;
    if (idx < n4) {
        out4[idx] = make_float4(v, v, v, v);
    }
    if (idx < n_tail) {                    // n_tail = 0 for this problem
        out_tail[idx] = v;
    }
}

extern "C" void kernel_launch(void* const* d_in, const int* in_sizes, int n_in,
                              void* d_out, int out_size) {
    (void)d_in; (void)in_sizes; (void)n_in;
    if (out_size <= 0) return;

    float* out = (float*)d_out;
    int n4 = out_size >> 2;            // 204800
    int n_tail = out_size & 3;         // 0
    float* tail_ptr = out + (size_t)n4 * 4;

    const int threads = 256;
    int blocks = (n4 + threads - 1) / threads;  // 800
    if (blocks < 1) blocks = 1;

    fill_neglog50_kernel<<<blocks, threads>>>(
        (float4*)out, n4, tail_ptr, n_tail);
}